// round 8
// baseline (speedup 1.0000x reference)
#include <cuda_runtime.h>
#include <cuda_bf16.h>
#include <math.h>
#include <cstdint>

#define N_NODES 20000
#define N_EDGES 600000
#define HDIM 128
#define NHEADS 4
#define EB 4688   // ceil(600000/128)

// ---------------- scratch -----------------------------------------------------
__device__ float    g_P[N_NODES * HDIM];
__device__ float    g_num[N_NODES * HDIM];
__device__ float    g_den[N_NODES * NHEADS];

// pre-split, pre-swizzled hE tiles: [block][chunk][16KB]
__device__ __align__(16) char g_hEh[(size_t)EB * 4 * 16384];
__device__ __align__(16) char g_hEl[(size_t)EB * 4 * 16384];

__device__ __align__(16) __nv_bfloat16 g_wv1h[32768], g_wv1l[32768];
__device__ __align__(16) __nv_bfloat16 g_wv2h[16384], g_wv2l[16384];
__device__ __align__(16) __nv_bfloat16 g_wv3h[16384], g_wv3l[16384];
__device__ __align__(16) __nv_bfloat16 g_wb1h[32768], g_wb1l[32768];
__device__ __align__(16) __nv_bfloat16 g_wb2h[16384], g_wb2l[16384];
__device__ __align__(16) __nv_bfloat16 g_wb3h[2048],  g_wb3l[2048];

// ---------------- helpers -----------------------------------------------------
__device__ __forceinline__ float gelu_f(float x) {
    return 0.5f * x * (1.0f + erff(x * 0.70710678118654752440f));
}
__device__ __forceinline__ void split2(float a, float b, unsigned &hi, unsigned &lo) {
    __nv_bfloat16 ha = __float2bfloat16(a), hb = __float2bfloat16(b);
    float ra = a - __bfloat162float(ha), rb = b - __bfloat162float(hb);
    __nv_bfloat162 th; th.x = ha; th.y = hb;
    __nv_bfloat162 tl = __floats2bfloat162_rn(ra, rb);
    hi = *reinterpret_cast<unsigned*>(&th);
    lo = *reinterpret_cast<unsigned*>(&tl);
}
__device__ __forceinline__ uint32_t smem_to_u32(const void* p) {
    uint32_t a;
    asm("{ .reg .u64 t; cvta.to.shared.u64 t, %1; cvt.u32.u64 %0, t; }" : "=r"(a) : "l"(p));
    return a;
}
__device__ __forceinline__ unsigned sw128(unsigned byte) {
    return byte ^ ((byte >> 3) & 0x70);
}

// ---------------- cp.async ------------------------------------------------------
__device__ __forceinline__ void cp16(uint32_t dst, const void* src) {
    asm volatile("cp.async.cg.shared.global [%0], [%1], 16;" :: "r"(dst), "l"(src));
}
#define CP_COMMIT() asm volatile("cp.async.commit_group;" ::: "memory")
#define CP_WAIT0()  asm volatile("cp.async.wait_group 0;" ::: "memory")
#define CP_WAIT1()  asm volatile("cp.async.wait_group 1;" ::: "memory")

__device__ __forceinline__ void cpa16k(uint32_t dst, const char* src, int tid) {
#pragma unroll
    for (int j = 0; j < 4; ++j)
        cp16(dst + tid * 16 + j * 4096, src + tid * 16 + j * 4096);
}

// ---------------- mma.sync primitives ------------------------------------------
__device__ __forceinline__ void ldsm4(unsigned r[4], uint32_t addr) {
    asm volatile("ldmatrix.sync.aligned.m8n8.x4.shared.b16 {%0,%1,%2,%3}, [%4];"
        : "=r"(r[0]), "=r"(r[1]), "=r"(r[2]), "=r"(r[3]) : "r"(addr));
}
__device__ __forceinline__ void mma_bf16(float c[4], const unsigned a[4], const unsigned b[2]) {
    asm volatile("mma.sync.aligned.m16n8k16.row.col.f32.bf16.bf16.f32 "
        "{%0,%1,%2,%3}, {%4,%5,%6,%7}, {%8,%9}, {%0,%1,%2,%3};"
        : "+f"(c[0]), "+f"(c[1]), "+f"(c[2]), "+f"(c[3])
        : "r"(a[0]), "r"(a[1]), "r"(a[2]), "r"(a[3]), "r"(b[0]), "r"(b[1]));
}

// smem byte offsets
#define OFF_CE   0
#define OFF_SEW  512
#define OFF_BUF(b) (4096 + (b) * 98304)   /* A h/l | Bb h/l | Bv h/l : 96KB each */
#define OFF_T0B  4096
#define OFF_T0V  69632
#define OFF_W0   135168
#define OFF_W1   167936
#define SMEM_MM  200704

// one K=64 chunk, 3-term split; tiles 128x64 bf16 SW128 (128B pitch)
__device__ __forceinline__ void chunk_mma(float acc[4][4][4],
                                          uint32_t Ah, uint32_t Al,
                                          uint32_t Bh, uint32_t Bl,
                                          int wm, int wn, int lid) {
    int g = lid >> 3, r = lid & 7;
    int am = (g & 1) * 8 + r, ak = (g >> 1) * 8;
    int bn = (g >> 1) * 8 + r, bk = (g & 1) * 8;
#pragma unroll
    for (int ks = 0; ks < 4; ++ks) {
        int kb = ks * 16;
        unsigned Af[2][4][4], Bf[2][4][2];
#pragma unroll
        for (int s = 0; s < 2; ++s) {
            uint32_t Ab = s ? Al : Ah;
#pragma unroll
            for (int ms = 0; ms < 4; ++ms) {
                unsigned byte = (unsigned)((wm * 64 + ms * 16 + am) * 128 + (kb + ak) * 2);
                ldsm4(Af[s][ms], Ab + sw128(byte));
            }
            uint32_t Bb = s ? Bl : Bh;
#pragma unroll
            for (int np = 0; np < 2; ++np) {
                unsigned byte = (unsigned)((wn * 32 + np * 16 + bn) * 128 + (kb + bk) * 2);
                unsigned t[4];
                ldsm4(t, Bb + sw128(byte));
                Bf[s][np*2][0] = t[0]; Bf[s][np*2][1] = t[1];
                Bf[s][np*2+1][0] = t[2]; Bf[s][np*2+1][1] = t[3];
            }
        }
#pragma unroll
        for (int ms = 0; ms < 4; ++ms)
#pragma unroll
            for (int ns = 0; ns < 4; ++ns) {
                mma_bf16(acc[ms][ns], Af[0][ms], Bf[0][ns]);
                mma_bf16(acc[ms][ns], Af[0][ms], Bf[1][ns]);
                mma_bf16(acc[ms][ns], Af[1][ms], Bf[0][ns]);
            }
    }
}

// fused L1: A fragments loaded once, applied to bias and value weight tiles
__device__ __forceinline__ void chunk_mma2(float accb[4][4][4], float accv[4][4][4],
                                           uint32_t Ah, uint32_t Al,
                                           uint32_t Bbh, uint32_t Bbl,
                                           uint32_t Bvh, uint32_t Bvl,
                                           int wm, int wn, int lid) {
    int g = lid >> 3, r = lid & 7;
    int am = (g & 1) * 8 + r, ak = (g >> 1) * 8;
    int bn = (g >> 1) * 8 + r, bk = (g & 1) * 8;
#pragma unroll
    for (int ks = 0; ks < 4; ++ks) {
        int kb = ks * 16;
        unsigned Af0[4][4], Af1[4][4];
#pragma unroll
        for (int ms = 0; ms < 4; ++ms) {
            unsigned byte = (unsigned)((wm * 64 + ms * 16 + am) * 128 + (kb + ak) * 2);
            ldsm4(Af0[ms], Ah + sw128(byte));
            ldsm4(Af1[ms], Al + sw128(byte));
        }
        unsigned bbyte = (unsigned)((wn * 32 + bn) * 128 + (kb + bk) * 2);
        unsigned bbyte2 = (unsigned)((wn * 32 + 16 + bn) * 128 + (kb + bk) * 2);
#pragma unroll
        for (int np = 0; np < 2; ++np) {
            unsigned byt = np ? bbyte2 : bbyte;
            unsigned th[4], tl[4];
            // ---- bias ----
            ldsm4(th, Bbh + sw128(byt));
            ldsm4(tl, Bbl + sw128(byt));
            {
                unsigned bh0[2] = {th[0], th[1]}, bh1[2] = {th[2], th[3]};
                unsigned bl0[2] = {tl[0], tl[1]}, bl1[2] = {tl[2], tl[3]};
#pragma unroll
                for (int ms = 0; ms < 4; ++ms) {
                    mma_bf16(accb[ms][np*2],   Af0[ms], bh0);
                    mma_bf16(accb[ms][np*2],   Af0[ms], bl0);
                    mma_bf16(accb[ms][np*2],   Af1[ms], bh0);
                    mma_bf16(accb[ms][np*2+1], Af0[ms], bh1);
                    mma_bf16(accb[ms][np*2+1], Af0[ms], bl1);
                    mma_bf16(accb[ms][np*2+1], Af1[ms], bh1);
                }
            }
            // ---- value ----
            ldsm4(th, Bvh + sw128(byt));
            ldsm4(tl, Bvl + sw128(byt));
            {
                unsigned bh0[2] = {th[0], th[1]}, bh1[2] = {th[2], th[3]};
                unsigned bl0[2] = {tl[0], tl[1]}, bl1[2] = {tl[2], tl[3]};
#pragma unroll
                for (int ms = 0; ms < 4; ++ms) {
                    mma_bf16(accv[ms][np*2],   Af0[ms], bh0);
                    mma_bf16(accv[ms][np*2],   Af0[ms], bl0);
                    mma_bf16(accv[ms][np*2],   Af1[ms], bh0);
                    mma_bf16(accv[ms][np*2+1], Af0[ms], bh1);
                    mma_bf16(accv[ms][np*2+1], Af0[ms], bl1);
                    mma_bf16(accv[ms][np*2+1], Af1[ms], bh1);
                }
            }
        }
    }
}

// logits variant: n0-7 only, B tile 16-row padded (2KB per h/l chunk)
__device__ __forceinline__ void chunk_mma_log(float accl[4][4],
                                              uint32_t Ah, uint32_t Al,
                                              uint32_t Bh, uint32_t Bl,
                                              int wm, int lid) {
    int g = lid >> 3, r = lid & 7;
    int am = (g & 1) * 8 + r, ak = (g >> 1) * 8;
    int bn = (g >> 1) * 8 + r, bk = (g & 1) * 8;
#pragma unroll
    for (int ks = 0; ks < 4; ++ks) {
        int kb = ks * 16;
        unsigned Af[2][4][4], Bf[2][2];
#pragma unroll
        for (int s = 0; s < 2; ++s) {
            uint32_t Ab = s ? Al : Ah;
#pragma unroll
            for (int ms = 0; ms < 4; ++ms) {
                unsigned byte = (unsigned)((wm * 64 + ms * 16 + am) * 128 + (kb + ak) * 2);
                ldsm4(Af[s][ms], Ab + sw128(byte));
            }
            unsigned byte = (unsigned)(bn * 128 + (kb + bk) * 2);
            unsigned t[4];
            ldsm4(t, (s ? Bl : Bh) + sw128(byte));
            Bf[s][0] = t[0]; Bf[s][1] = t[1];
        }
#pragma unroll
        for (int ms = 0; ms < 4; ++ms) {
            mma_bf16(accl[ms], Af[0][ms], Bf[0]);
            mma_bf16(accl[ms], Af[0][ms], Bf[1]);
            mma_bf16(accl[ms], Af[1][ms], Bf[0]);
        }
    }
}

// acc + add -> gelu -> split -> T tiles (hi @ +ch*16K, lo @ +32K+ch*16K)
__device__ __forceinline__ void epi_store(float acc[4][4][4], char* T,
                                          const float* __restrict__ addv,
                                          const int* __restrict__ ce, bool perrow,
                                          int wm, int wn, int lid) {
#pragma unroll
    for (int ms = 0; ms < 4; ++ms) {
        int r0 = wm * 64 + ms * 16 + (lid >> 2), r1 = r0 + 8;
#pragma unroll
        for (int ns = 0; ns < 4; ++ns) {
            int n = wn * 32 + ns * 8 + (lid & 3) * 2;
            const float* a0 = perrow ? (addv + (size_t)ce[r0] * 128 + n) : (addv + n);
            const float* a1 = perrow ? (addv + (size_t)ce[r1] * 128 + n) : (addv + n);
            float o0 = gelu_f(acc[ms][ns][0] + a0[0]);
            float o1 = gelu_f(acc[ms][ns][1] + a0[1]);
            float o2 = gelu_f(acc[ms][ns][2] + a1[0]);
            float o3 = gelu_f(acc[ms][ns][3] + a1[1]);
            unsigned h01, l01, h23, l23;
            split2(o0, o1, h01, l01);
            split2(o2, o3, h23, l23);
            int ch = n >> 6, kk = n & 63;
            unsigned s0 = sw128((unsigned)(r0 * 128 + kk * 2));
            unsigned s1 = sw128((unsigned)(r1 * 128 + kk * 2));
            char* th = T + ch * 16384;
            *(unsigned*)(th + s0) = h01;          *(unsigned*)(th + s1) = h23;
            *(unsigned*)(th + 32768 + s0) = l01;  *(unsigned*)(th + 32768 + s1) = l23;
        }
    }
}

// ---------------- setup kernels -----------------------------------------------
extern "C" __global__ void __launch_bounds__(128)
k_init() {
    int i = blockIdx.x * blockDim.x + threadIdx.x;
    if (i < N_NODES * HDIM) g_num[i] = 0.0f;
    if (i < N_NODES * NHEADS) g_den[i] = 0.0f;
}

extern "C" __global__ void __launch_bounds__(256)
k_esplit(const float* __restrict__ hE) {
    const float4* hE4 = reinterpret_cast<const float4*>(hE);
    const size_t total = (size_t)EB * 128 * 64;
#pragma unroll
    for (int j = 0; j < 4; ++j) {
        size_t idx = (size_t)blockIdx.x * 1024 + j * 256 + threadIdx.x;
        if (idx >= total) continue;
        size_t e = idx >> 6; int q = (int)(idx & 63);
        int c = q >> 4, q15 = q & 15;
        int m = (int)(e & 127); size_t eb = e >> 7;
        float4 v = make_float4(0.f, 0.f, 0.f, 0.f);
        if (e < N_EDGES) v = hE4[e * 64 + (size_t)q];
        unsigned sw = sw128((unsigned)(m * 128 + q15 * 8));
        size_t tb = (eb * 4 + (size_t)c) * 16384;
        unsigned h01, l01, h23, l23;
        split2(v.x, v.y, h01, l01);
        split2(v.z, v.w, h23, l23);
        *(uint2*)(g_hEh + tb + sw) = make_uint2(h01, h23);
        *(uint2*)(g_hEl + tb + sw) = make_uint2(l01, l23);
    }
}

extern "C" __global__ void __launch_bounds__(256)
k_wconv(const float* __restrict__ W, __nv_bfloat16* __restrict__ hi,
        __nv_bfloat16* __restrict__ lo, int nrows_pad, int nrows_real,
        int nchunks, int rstride, int coff) {
    int idx = blockIdx.x * 256 + threadIdx.x;
    int tile = nrows_pad * 64;
    if (idx >= tile * nchunks) return;
    int c = idx / tile, rem = idx % tile;
    int n = rem / 64, kk = rem % 64;
    float x = (n < nrows_real) ? W[n * rstride + coff + c * 64 + kk] : 0.0f;
    __nv_bfloat16 h = __float2bfloat16(x);
    float r = x - __bfloat162float(h);
    unsigned sw = sw128((unsigned)(n * 128 + kk * 2));
    hi[c * tile + sw / 2] = h;
    lo[c * tile + sw / 2] = __float2bfloat16(r);
}

template<int K, int XP>
__device__ __forceinline__ void gemm_stage(float acc[64], const float* __restrict__ wrow,
                                           const float* __restrict__ xs) {
#pragma unroll 1
    for (int k = 0; k < K; k += 4) {
        float4 wv = *reinterpret_cast<const float4*>(wrow + k);
#pragma unroll
        for (int e = 0; e < 64; ++e) {
            float4 xv = *reinterpret_cast<const float4*>(xs + e * XP + k);
            acc[e] = fmaf(wv.x, xv.x, acc[e]);
            acc[e] = fmaf(wv.y, xv.y, acc[e]);
            acc[e] = fmaf(wv.z, xv.z, acc[e]);
            acc[e] = fmaf(wv.w, xv.w, acc[e]);
        }
    }
}

extern "C" __global__ void __launch_bounds__(128)
k_pre(const float* __restrict__ hV, const float* __restrict__ Wb1,
      const float* __restrict__ bb1) {
    __shared__ float xs[64 * HDIM];
    int j = threadIdx.x;
    int n0 = blockIdx.x * 64;
    int cnt = N_NODES - n0; if (cnt > 64) cnt = 64;
    const float4* src = reinterpret_cast<const float4*>(hV + (size_t)n0 * HDIM);
    float4* dst = reinterpret_cast<float4*>(xs);
    for (int i = j; i < 64 * HDIM / 4; i += 128) {
        int n = i / (HDIM / 4);
        dst[i] = (n < cnt) ? src[i] : make_float4(0.f, 0.f, 0.f, 0.f);
    }
    __syncthreads();
    float acc[64];
    float b = bb1[j];
#pragma unroll
    for (int e = 0; e < 64; ++e) acc[e] = b;
    gemm_stage<HDIM, HDIM>(acc, Wb1 + j * 384, xs);
#pragma unroll
    for (int e = 0; e < 64; ++e)
        if (e < cnt) g_P[(size_t)(n0 + e) * HDIM + j] = acc[e];
}

// ---------------- FUSED edge kernel (both MLPs, one pass) ----------------------
extern "C" __global__ void __launch_bounds__(256)
k_edge_fused(const int* __restrict__ cid,
             const float* __restrict__ bb2, const float* __restrict__ bb3,
             const float* __restrict__ bv1, const float* __restrict__ bv2,
             const float* __restrict__ bv3) {
    extern __shared__ char sm[];
    uint32_t smb = smem_to_u32(sm);
    int tid = threadIdx.x, wid = tid >> 5, lid = tid & 31;
    int wm = wid & 1, wn = wid >> 1;
    size_t e0 = (size_t)blockIdx.x * 128;
    size_t eb = (size_t)blockIdx.x;
    int* ce = (int*)(sm + OFF_CE);
    float* sew = (float*)(sm + OFF_SEW);
    if (tid < 128) ce[tid] = (e0 + tid < N_EDGES) ? cid[e0 + tid] : 0;

    float accb[4][4][4], accv[4][4][4];
#pragma unroll
    for (int i = 0; i < 4; ++i)
#pragma unroll
        for (int j2 = 0; j2 < 4; ++j2)
#pragma unroll
            for (int k = 0; k < 4; ++k) { accb[i][j2][k] = 0.f; accv[i][j2][k] = 0.f; }

    // ---- L1: both MLPs, shared A (K=256, 4 chunks, triple-tile double buffer) ----
    {
        uint32_t B0 = smb + OFF_BUF(0);
        cpa16k(B0,          g_hEh + eb * 4 * 16384, tid);
        cpa16k(B0 + 16384,  g_hEl + eb * 4 * 16384, tid);
        cpa16k(B0 + 32768,  (const char*)g_wb1h, tid);
        cpa16k(B0 + 49152,  (const char*)g_wb1l, tid);
        cpa16k(B0 + 65536,  (const char*)g_wv1h, tid);
        cpa16k(B0 + 81920,  (const char*)g_wv1l, tid);
        CP_COMMIT();
    }
    for (int c = 0; c < 4; ++c) {
        if (c < 3) {
            uint32_t B = smb + OFF_BUF((c + 1) & 1);
            cpa16k(B,          g_hEh + (eb * 4 + c + 1) * 16384, tid);
            cpa16k(B + 16384,  g_hEl + (eb * 4 + c + 1) * 16384, tid);
            cpa16k(B + 32768,  (const char*)g_wb1h + (size_t)(c + 1) * 16384, tid);
            cpa16k(B + 49152,  (const char*)g_wb1l + (size_t)(c + 1) * 16384, tid);
            cpa16k(B + 65536,  (const char*)g_wv1h + (size_t)(c + 1) * 16384, tid);
            cpa16k(B + 81920,  (const char*)g_wv1l + (size_t)(c + 1) * 16384, tid);
            CP_COMMIT();
            CP_WAIT1();
        } else CP_WAIT0();
        __syncthreads();
        uint32_t B = smb + OFF_BUF(c & 1);
        chunk_mma2(accb, accv, B, B + 16384, B + 32768, B + 49152,
                   B + 65536, B + 81920, wm, wn, lid);
        __syncthreads();
    }
    // t1_bias = gelu(D + P[ce]); t1_val = gelu(D + bv1)  (A buffers dead -> T tiles)
    epi_store(accb, sm + OFF_T0B, g_P, ce, true,  wm, wn, lid);
    epi_store(accv, sm + OFF_T0V, bv1, ce, false, wm, wn, lid);
    __syncthreads();

    uint32_t W0 = smb + OFF_W0, W1 = smb + OFF_W1;
    uint32_t T0B = smb + OFF_T0B, T0V = smb + OFF_T0V;

    // ---- bias L2: t1b @ Wb2^T ----
#pragma unroll
    for (int i = 0; i < 4; ++i)
#pragma unroll
        for (int j2 = 0; j2 < 4; ++j2)
#pragma unroll
            for (int k = 0; k < 4; ++k) accb[i][j2][k] = 0.f;
    cpa16k(W0,          (const char*)g_wb2h, tid);
    cpa16k(W0 + 16384,  (const char*)g_wb2l, tid);
    CP_COMMIT();
    cpa16k(W1,          (const char*)g_wb2h + 16384, tid);
    cpa16k(W1 + 16384,  (const char*)g_wb2l + 16384, tid);
    CP_COMMIT();
    CP_WAIT1(); __syncthreads();
    chunk_mma(accb, T0B,          T0B + 32768,          W0, W0 + 16384, wm, wn, lid);
    CP_WAIT0(); __syncthreads();
    chunk_mma(accb, T0B + 16384,  T0B + 49152,          W1, W1 + 16384, wm, wn, lid);
    __syncthreads();
    epi_store(accb, sm + OFF_T0B, bb2, ce, false, wm, wn, lid);   // T1b overwrites T0b
    __syncthreads();

    // ---- bias L3: logits (8KB Wb3 tiles into W0) + prefetch value B2 c0 into W1 ----
    {
        const char* W3h = (const char*)g_wb3h;
        const char* W3l = (const char*)g_wb3l;
#pragma unroll
        for (int j = 0; j < 2; ++j) {
            int i = tid + j * 256;        // 0..511
            int quad = i >> 7, off = (i & 127) * 16;
            const char* src = (quad == 0) ? (W3h + off) :
                              (quad == 1) ? (W3l + off) :
                              (quad == 2) ? (W3h + 2048 + off) : (W3l + 2048 + off);
            uint32_t dst = W0 + quad * 2048 + off;
            cp16(dst, src);
        }
        CP_COMMIT();
        cpa16k(W1,         (const char*)g_wv2h, tid);
        cpa16k(W1 + 16384, (const char*)g_wv2l, tid);
        CP_COMMIT();
        CP_WAIT1(); __syncthreads();      // Wb3 ready (value B2 c0 may still fly)
    }
    {
        float accl[4][4];
#pragma unroll
        for (int i = 0; i < 4; ++i)
#pragma unroll
            for (int k = 0; k < 4; ++k) accl[i][k] = 0.f;
        if (wn == 0) {
            chunk_mma_log(accl, T0B,         T0B + 32768, W0,        W0 + 2048, wm, lid);
            chunk_mma_log(accl, T0B + 16384, T0B + 49152, W0 + 4096, W0 + 6144, wm, lid);
        }
        if (wn == 0 && (lid & 3) < 2) {
            const float rs = 0.17677669529663687f;  // 1/sqrt(32)
            int n = (lid & 3) * 2;
            float bn0 = bb3[n], bn1 = bb3[n + 1];
#pragma unroll
            for (int ms = 0; ms < 4; ++ms) {
                int r0 = wm * 64 + ms * 16 + (lid >> 2), r1 = r0 + 8;
                float w0 = expf((accl[ms][0] + bn0) * rs);
                float w1 = expf((accl[ms][1] + bn1) * rs);
                float w2 = expf((accl[ms][2] + bn0) * rs);
                float w3 = expf((accl[ms][3] + bn1) * rs);
                sew[r0 * 4 + n] = w0;     sew[r0 * 4 + n + 1] = w1;
                sew[r1 * 4 + n] = w2;     sew[r1 * 4 + n + 1] = w3;
                if (e0 + r0 < N_EDGES) {
                    atomicAdd(&g_den[(size_t)ce[r0] * 4 + n], w0);
                    atomicAdd(&g_den[(size_t)ce[r0] * 4 + n + 1], w1);
                }
                if (e0 + r1 < N_EDGES) {
                    atomicAdd(&g_den[(size_t)ce[r1] * 4 + n], w2);
                    atomicAdd(&g_den[(size_t)ce[r1] * 4 + n + 1], w3);
                }
            }
        }
    }
    __syncthreads();

    // ---- value L2: t1v @ Wv2^T ----
#pragma unroll
    for (int i = 0; i < 4; ++i)
#pragma unroll
        for (int j2 = 0; j2 < 4; ++j2)
#pragma unroll
            for (int k = 0; k < 4; ++k) accb[i][j2][k] = 0.f;
    cpa16k(W0,          (const char*)g_wv2h + 16384, tid);    // c1 (Wb3 region dead)
    cpa16k(W0 + 16384,  (const char*)g_wv2l + 16384, tid);
    CP_COMMIT();
    CP_WAIT1(); __syncthreads();     // W1 (c0) ready
    chunk_mma(accb, T0V,          T0V + 32768, W1, W1 + 16384, wm, wn, lid);
    CP_WAIT0(); __syncthreads();
    chunk_mma(accb, T0V + 16384,  T0V + 49152, W0, W0 + 16384, wm, wn, lid);
    __syncthreads();
    epi_store(accb, sm + OFF_T0V, bv2, ce, false, wm, wn, lid);  // T1v overwrites T0v
    __syncthreads();

    // ---- value L3: V = t2v @ Wv3^T; exp-weighted scatter ----
#pragma unroll
    for (int i = 0; i < 4; ++i)
#pragma unroll
        for (int j2 = 0; j2 < 4; ++j2)
#pragma unroll
            for (int k = 0; k < 4; ++k) accb[i][j2][k] = 0.f;
    cpa16k(W1,          (const char*)g_wv3h, tid);
    cpa16k(W1 + 16384,  (const char*)g_wv3l, tid);
    CP_COMMIT();
    cpa16k(W0,          (const char*)g_wv3h + 16384, tid);
    cpa16k(W0 + 16384,  (const char*)g_wv3l + 16384, tid);
    CP_COMMIT();
    CP_WAIT1(); __syncthreads();
    chunk_mma(accb, T0V,          T0V + 32768, W1, W1 + 16384, wm, wn, lid);
    CP_WAIT0(); __syncthreads();
    chunk_mma(accb, T0V + 16384,  T0V + 49152, W0, W0 + 16384, wm, wn, lid);

#pragma unroll
    for (int ms = 0; ms < 4; ++ms) {
        int r0 = wm * 64 + ms * 16 + (lid >> 2), r1 = r0 + 8;
        float ew0 = sew[r0 * 4 + wn], ew1 = sew[r1 * 4 + wn];
        bool v0 = (e0 + r0) < N_EDGES, v1 = (e0 + r1) < N_EDGES;
        float* d0 = g_num + (size_t)ce[r0] * 128;
        float* d1 = g_num + (size_t)ce[r1] * 128;
#pragma unroll
        for (int ns = 0; ns < 4; ++ns) {
            int n = wn * 32 + ns * 8 + (lid & 3) * 2;
            float bn0 = bv3[n], bn1 = bv3[n + 1];
            if (v0) {
                atomicAdd(d0 + n,     ew0 * (accb[ms][ns][0] + bn0));
                atomicAdd(d0 + n + 1, ew0 * (accb[ms][ns][1] + bn1));
            }
            if (v1) {
                atomicAdd(d1 + n,     ew1 * (accb[ms][ns][2] + bn0));
                atomicAdd(d1 + n + 1, ew1 * (accb[ms][ns][3] + bn1));
            }
        }
    }
}

// ---------------- output projection --------------------------------------------
extern "C" __global__ void __launch_bounds__(128)
k_out(const float* __restrict__ Wo, float* __restrict__ out) {
    __shared__ float xs[64 * HDIM];
    int j = threadIdx.x;
    int n0 = blockIdx.x * 64;
    int cnt = N_NODES - n0; if (cnt > 64) cnt = 64;
    for (int i = j; i < 64 * HDIM; i += 128) {
        int n = i >> 7, c = i & 127;
        float v = 0.f;
        if (n < cnt) {
            float d = g_den[(size_t)(n0 + n) * NHEADS + (c >> 5)];
            float nm = g_num[(size_t)(n0 + n) * HDIM + c];
            v = (d > 0.f) ? nm / d : 0.f;
        }
        xs[i] = v;
    }
    __syncthreads();
    float acc[64];
#pragma unroll
    for (int e = 0; e < 64; ++e) acc[e] = 0.f;
    gemm_stage<HDIM, HDIM>(acc, Wo + j * HDIM, xs);
#pragma unroll
    for (int e = 0; e < 64; ++e)
        if (e < cnt) out[(size_t)(n0 + e) * HDIM + j] = acc[e];
}

// ---------------- launch --------------------------------------------------------
extern "C" void kernel_launch(void* const* d_in, const int* in_sizes, int n_in,
                              void* d_out, int out_size) {
    const float* hV  = (const float*)d_in[0];
    const float* hE  = (const float*)d_in[1];
    const float* Wv1 = (const float*)d_in[2];
    const float* bv1 = (const float*)d_in[3];
    const float* Wv2 = (const float*)d_in[4];
    const float* bv2 = (const float*)d_in[5];
    const float* Wv3 = (const float*)d_in[6];
    const float* bv3 = (const float*)d_in[7];
    const float* Wb1 = (const float*)d_in[8];
    const float* bb1 = (const float*)d_in[9];
    const float* Wb2 = (const float*)d_in[10];
    const float* bb2 = (const float*)d_in[11];
    const float* Wb3 = (const float*)d_in[12];
    const float* bb3 = (const float*)d_in[13];
    const float* Wo  = (const float*)d_in[14];
    const int*   cid = (const int*)d_in[15];
    float* out = (float*)d_out;

    __nv_bfloat16 *wv1h, *wv1l, *wv2h, *wv2l, *wv3h, *wv3l;
    __nv_bfloat16 *wb1h, *wb1l, *wb2h, *wb2l, *wb3h, *wb3l;
    cudaGetSymbolAddress((void**)&wv1h, g_wv1h); cudaGetSymbolAddress((void**)&wv1l, g_wv1l);
    cudaGetSymbolAddress((void**)&wv2h, g_wv2h); cudaGetSymbolAddress((void**)&wv2l, g_wv2l);
    cudaGetSymbolAddress((void**)&wv3h, g_wv3h); cudaGetSymbolAddress((void**)&wv3l, g_wv3l);
    cudaGetSymbolAddress((void**)&wb1h, g_wb1h); cudaGetSymbolAddress((void**)&wb1l, g_wb1l);
    cudaGetSymbolAddress((void**)&wb2h, g_wb2h); cudaGetSymbolAddress((void**)&wb2l, g_wb2l);
    cudaGetSymbolAddress((void**)&wb3h, g_wb3h); cudaGetSymbolAddress((void**)&wb3l, g_wb3l);

    cudaFuncSetAttribute(k_edge_fused, cudaFuncAttributeMaxDynamicSharedMemorySize, SMEM_MM);

    k_init<<<(N_NODES * HDIM + 127) / 128, 128>>>();
    k_wconv<<<128, 256>>>(Wv1, wv1h, wv1l, 128, 128, 4, 256, 0);
    k_wconv<<<64,  256>>>(Wv2, wv2h, wv2l, 128, 128, 2, 128, 0);
    k_wconv<<<64,  256>>>(Wv3, wv3h, wv3l, 128, 128, 2, 128, 0);
    k_wconv<<<128, 256>>>(Wb1, wb1h, wb1l, 128, 128, 4, 384, 128);
    k_wconv<<<64,  256>>>(Wb2, wb2h, wb2l, 128, 128, 2, 128, 0);
    k_wconv<<<8,   256>>>(Wb3, wb3h, wb3l, 16, 4, 2, 128, 0);
    k_esplit<<<(EB * 128 * 64 + 1023) / 1024, 256>>>(hE);
    k_pre<<<(N_NODES + 63) / 64, 128>>>(hV, Wb1, bb1);

    k_edge_fused<<<EB, 256, SMEM_MM>>>(cid, bb2, bb3, bv1, bv2, bv3);
    k_out<<<(N_NODES + 63) / 64, 128>>>(Wo, out);
}